// round 1
// baseline (speedup 1.0000x reference)
#include <cuda_runtime.h>
#include <cuda_bf16.h>

// Packed fp32x2 FMA (Blackwell sm_100+). Only reachable via PTX.
__device__ __forceinline__ void fma2(unsigned long long& d,
                                     unsigned long long a,
                                     unsigned long long b) {
    asm("fma.rn.f32x2 %0, %1, %2, %0;" : "+l"(d) : "l"(a), "l"(b));
}

// ---------------------------------------------------------------------------
// Main kernel: block-diagonal 1x1 conv.
// z[b, k*32+d, p] = sum_c w[k, d, c] * x[b, k*32+c, p]
// Grid: (16 pixel-chunks, 8 blocks k, 16 batches b), 256 threads.
// Each thread: 4 consecutive pixels (2 f32x2 pairs), all 32 output channels.
// ---------------------------------------------------------------------------
__global__ __launch_bounds__(256)
void conv_blocks_kernel(const float* __restrict__ x,
                        const float* __restrict__ w,
                        float* __restrict__ z) {
    const int tid = threadIdx.x;
    const int k   = blockIdx.y;
    const int b   = blockIdx.z;

    // Shared: w transposed + duplicated into packed (w,w) pairs.
    // Layout w2s[c*32 + d] = pack(w[k, d, c], w[k, d, c])
    __shared__ unsigned long long w2s[1024];
    const float* wk = w + k * 1024;
    for (int i = tid; i < 1024; i += 256) {
        unsigned int u = __float_as_uint(wk[i]);           // i = d*32 + c
        w2s[(i & 31) * 32 + (i >> 5)] =
            ((unsigned long long)u << 32) | (unsigned long long)u;
    }
    __syncthreads();

    // Pixel base for this thread: 4 consecutive pixels (16B aligned).
    const long p0   = ((long)blockIdx.x * 256 + tid) * 4;
    const long base = ((long)b * 256 + (long)k * 32) * 16384L;

    const ulonglong2* __restrict__ xp =
        reinterpret_cast<const ulonglong2*>(x + base + p0);
    ulonglong2* __restrict__ zp =
        reinterpret_cast<ulonglong2*>(z + base + p0);

    // 32 output channels x 2 pixel-pairs of f32x2 accumulators.
    unsigned long long acc0[32], acc1[32];
#pragma unroll
    for (int d = 0; d < 32; ++d) { acc0[d] = 0ULL; acc1[d] = 0ULL; }

#pragma unroll 8
    for (int c = 0; c < 32; ++c) {
        const ulonglong2 xv = xp[(long)c * 4096];  // LDG.128: pixels p0..p0+3, channel c
        const unsigned long long* wrow = &w2s[c * 32];
#pragma unroll
        for (int d = 0; d < 32; ++d) {
            const unsigned long long wv = wrow[d]; // LDS.64 broadcast, reused x2
            fma2(acc0[d], xv.x, wv);
            fma2(acc1[d], xv.y, wv);
        }
    }

#pragma unroll
    for (int d = 0; d < 32; ++d) {
        ulonglong2 o;
        o.x = acc0[d];
        o.y = acc1[d];
        zp[(long)d * 4096] = o;                    // STG.128, coalesced
    }
}

// ---------------------------------------------------------------------------
// slogdet tail: LU with partial pivoting, one warp per 32x32 block.
// Reference discards the sign, so log|det| = sum log|pivot|.
// out_tail[t] = logdet_in[t] + (sum_k log|det W_k|) * (128*128)
// ---------------------------------------------------------------------------
__global__ __launch_bounds__(256)
void logdet_kernel(const float* __restrict__ w,
                   const float* __restrict__ ld_in,
                   float* __restrict__ out_tail) {
    __shared__ float A[8][32][33];   // pad to 33 -> conflict-free column reads
    __shared__ float lds[8];

    const int tid  = threadIdx.x;
    const int m    = tid >> 5;       // matrix index (warp id)
    const int lane = tid & 31;

    // Load matrix m: A[m][r][c]
    for (int r = 0; r < 32; ++r)
        A[m][r][lane] = w[m * 1024 + r * 32 + lane];
    __syncwarp();

    float ldacc = 0.0f;
    for (int step = 0; step < 32; ++step) {
        // Partial pivot: argmax |A[r][step]| over r >= step.
        float v  = (lane >= step) ? fabsf(A[m][lane][step]) : -1.0f;
        int  idx = lane;
        for (int off = 16; off; off >>= 1) {
            float ov = __shfl_down_sync(0xffffffffu, v, off);
            int   oi = __shfl_down_sync(0xffffffffu, idx, off);
            if (ov > v) { v = ov; idx = oi; }
        }
        const int pr = __shfl_sync(0xffffffffu, idx, 0);

        if (pr != step) {            // row swap (each lane owns one column)
            float t = A[m][step][lane];
            A[m][step][lane] = A[m][pr][lane];
            A[m][pr][lane]   = t;
        }
        __syncwarp();

        const float piv = A[m][step][step];
        ldacc += logf(fabsf(piv));
        const float inv = 1.0f / piv;

        if (lane > step) {           // eliminate: lane owns row `lane`
            const float f = A[m][lane][step] * inv;
            for (int c = step + 1; c < 32; ++c)
                A[m][lane][c] -= f * A[m][step][c];
        }
        __syncwarp();
    }

    if (lane == 0) lds[m] = ldacc;
    __syncthreads();

    if (tid < 16) {
        float tot = 0.0f;
        for (int mm = 0; mm < 8; ++mm) tot += lds[mm];
        out_tail[tid] = ld_in[tid] + tot * 16384.0f;
    }
}

// ---------------------------------------------------------------------------
extern "C" void kernel_launch(void* const* d_in, const int* in_sizes, int n_in,
                              void* d_out, int out_size) {
    const float* x  = (const float*)d_in[0];   // [16, 256, 128, 128]
    const float* w  = (const float*)d_in[1];   // [8, 32, 32]
    const float* ld = (const float*)d_in[2];   // [16]
    float* out = (float*)d_out;

    const long zn = (long)in_sizes[0];         // 16*256*128*128 elements of z

    dim3 grid(16, 8, 16);                      // (pixel chunks, blocks k, batch b)
    conv_blocks_kernel<<<grid, 256>>>(x, w, out);
    logdet_kernel<<<1, 256>>>(w, ld, out + zn);
    (void)n_in; (void)out_size;
}

// round 3
// speedup vs baseline: 1.0852x; 1.0852x over previous
#include <cuda_runtime.h>
#include <cuda_bf16.h>

// Packed fp32x2 FMA (Blackwell sm_100+). Only reachable via PTX.
__device__ __forceinline__ void fma2(unsigned long long& d,
                                     unsigned long long a,
                                     unsigned long long b) {
    asm("fma.rn.f32x2 %0, %1, %2, %0;" : "+l"(d) : "l"(a), "l"(b));
}

#define N_CONV_CTAS 2048

// ---------------------------------------------------------------------------
// Fused kernel.
// CTAs [0, 2048): block-diagonal 1x1 conv.
//   z[b, k*32+d, p] = sum_c w[k, d, c] * x[b, k*32+c, p]
//   512 threads: lower half does d in [0,16), upper half d in [16,32),
//   SAME pixel range (x reuse via L1). Each thread: 4 pixels x 16 outputs.
// CTA 2048: logdet tail (one warp per 32x32 block, LU w/ partial pivot).
// ---------------------------------------------------------------------------
__global__ __launch_bounds__(512)
void fused_kernel(const float* __restrict__ x,
                  const float* __restrict__ w,
                  const float* __restrict__ ld_in,
                  float* __restrict__ out,
                  long zn) {
    __shared__ union SM {
        ulonglong2 w2[512];                 // conv: packed weight pairs (8 KB)
        struct {
            float A[8][32][33];             // logdet: padded matrices
            float lds[8];
        } lu;
    } sm;

    const int gid = blockIdx.x;
    const int tid = threadIdx.x;

    if (gid < N_CONV_CTAS) {
        // ---------------- conv path ----------------
        const int k    = (gid >> 4) & 7;
        const int b    = gid >> 7;
        const int t    = tid & 255;         // pixel-group index within CTA
        const int half = tid >> 8;          // 0: d 0..15, 1: d 16..31

        // Pack weights: w2[c*16 + j] = { pack2(w[2j][c]), pack2(w[2j+1][c]) }
        unsigned long long* w2u = reinterpret_cast<unsigned long long*>(sm.w2);
        const float* wk = w + k * 1024;
        for (int i = tid; i < 1024; i += 512) {          // i = d*32 + c
            const int d = i >> 5, c = i & 31;
            const unsigned long long u =
                (unsigned long long)__float_as_uint(wk[i]);
            w2u[(c * 16 + (d >> 1)) * 2 + (d & 1)] = (u << 32) | u;
        }
        __syncthreads();

        const long p0   = ((long)(gid & 15) * 256 + t) * 4;   // 4 px / thread
        const long base = ((long)b * 256 + (long)k * 32) * 16384L;

        const ulonglong2* __restrict__ xp =
            reinterpret_cast<const ulonglong2*>(x + base) + (p0 >> 2);

        // 16 outputs x 2 f32x2 pixel-pairs
        unsigned long long acc[32];
#pragma unroll
        for (int i = 0; i < 32; ++i) acc[i] = 0ULL;

        const ulonglong2* __restrict__ wbase = sm.w2 + half * 8;

#pragma unroll 4
        for (int c = 0; c < 32; ++c) {
            const ulonglong2 xv = xp[(long)c * 4096];   // LDG.128, coalesced
            const ulonglong2* wr = wbase + c * 16;
#pragma unroll
            for (int j = 0; j < 8; ++j) {
                const ulonglong2 wv = wr[j];            // LDS.128 broadcast
                fma2(acc[4 * j + 0], xv.x, wv.x);
                fma2(acc[4 * j + 1], xv.y, wv.x);
                fma2(acc[4 * j + 2], xv.x, wv.y);
                fma2(acc[4 * j + 3], xv.y, wv.y);
            }
        }

        ulonglong2* __restrict__ zp =
            reinterpret_cast<ulonglong2*>(out + base) + (p0 >> 2) +
            (long)half * 16 * 4096;
#pragma unroll
        for (int j = 0; j < 8; ++j) {
            zp[(long)(2 * j)     * 4096] = make_ulonglong2(acc[4 * j + 0], acc[4 * j + 1]);
            zp[(long)(2 * j + 1) * 4096] = make_ulonglong2(acc[4 * j + 2], acc[4 * j + 3]);
        }
    } else {
        // ---------------- logdet path (CTA 2048) ----------------
        // Warps 0..7 (tid < 256): LU w/ partial pivot on matrix m = warp id.
        // Reference discards the sign: log|det| = sum log|pivot|.
        const int m    = tid >> 5;
        const int lane = tid & 31;

        if (tid < 256) {
            for (int r = 0; r < 32; ++r)
                sm.lu.A[m][r][lane] = w[m * 1024 + r * 32 + lane];
            __syncwarp();

            float prod = 1.0f;   // product of pivot mantissas in [1,2)
            int   esum = 0;      // sum of pivot exponents
            for (int step = 0; step < 32; ++step) {
                // argmax |A[r][step]|, r >= step (abs-bits compare as uint)
                const unsigned v = (lane >= step)
                    ? (__float_as_uint(sm.lu.A[m][lane][step]) & 0x7fffffffu)
                    : 0u;
                const unsigned mx = __reduce_max_sync(0xffffffffu, v);
                const unsigned bal = __ballot_sync(0xffffffffu, v == mx);
                const int pr = __ffs(bal) - 1;

                if (pr != step) {            // swap rows (lane owns a column)
                    const float tswap = sm.lu.A[m][step][lane];
                    sm.lu.A[m][step][lane] = sm.lu.A[m][pr][lane];
                    sm.lu.A[m][pr][lane]   = tswap;
                }
                __syncwarp();

                const float piv = sm.lu.A[m][step][step];
                const unsigned pb = __float_as_uint(piv) & 0x7fffffffu;
                esum += (int)(pb >> 23) - 127;
                prod *= __uint_as_float((pb & 0x007fffffu) | 0x3f800000u);

                const float inv = 1.0f / piv;
                if (lane > step) {
                    const float f = sm.lu.A[m][lane][step] * inv;
                    for (int c2 = step + 1; c2 < 32; ++c2)
                        sm.lu.A[m][lane][c2] -= f * sm.lu.A[m][step][c2];
                }
                __syncwarp();
            }
            if (lane == 0)
                sm.lu.lds[m] = (float)esum * 0.6931471805599453f + logf(prod);
        }
        __syncthreads();                    // all 512 threads participate

        if (tid < 16) {
            float tot = 0.0f;
#pragma unroll
            for (int mm = 0; mm < 8; ++mm) tot += sm.lu.lds[mm];
            out[zn + tid] = ld_in[tid] + tot * 16384.0f;
        }
    }
}

// ---------------------------------------------------------------------------
extern "C" void kernel_launch(void* const* d_in, const int* in_sizes, int n_in,
                              void* d_out, int out_size) {
    const float* x  = (const float*)d_in[0];   // [16, 256, 128, 128]
    const float* w  = (const float*)d_in[1];   // [8, 32, 32]
    const float* ld = (const float*)d_in[2];   // [16]
    float* out = (float*)d_out;

    const long zn = (long)in_sizes[0];         // element count of z

    fused_kernel<<<N_CONV_CTAS + 1, 512>>>(x, w, ld, out, zn);
    (void)n_in; (void)out_size;
}

// round 5
// speedup vs baseline: 1.4682x; 1.3530x over previous
#include <cuda_runtime.h>
#include <cuda_bf16.h>

// Packed fp32x2 FMA (Blackwell sm_100+). Only reachable via PTX.
__device__ __forceinline__ void fma2(unsigned long long& d,
                                     unsigned long long a,
                                     unsigned long long b) {
    asm("fma.rn.f32x2 %0, %1, %2, %0;" : "+l"(d) : "l"(a), "l"(b));
}

// ---------------------------------------------------------------------------
// Fused kernel, 256 threads/CTA, 3 CTAs/SM (reg cap 85).
// gid 0          : logdet tail (runs in wave 1, hidden under conv CTAs).
// gid 1..8192    : block-diagonal 1x1 conv.
//   z[b, k*32+d, p] = sum_c w[k, d, c] * x[b, k*32+c, p]
//   CTA = 64 pixel-threads x 4 d-groups (8 outputs each), 4 px/thread.
//   Rotating depth-4 register prefetch on the c loop (MLP=4/warp).
// ---------------------------------------------------------------------------
__global__ __launch_bounds__(256, 3)
void fused_kernel(const float* __restrict__ x,
                  const float* __restrict__ w,
                  const float* __restrict__ ld_in,
                  float* __restrict__ out,
                  long zn) {
    __shared__ union SM {
        ulonglong2 w2[512];                 // conv: packed weight pairs (8 KB)
        struct {
            float A[8][32][33];             // logdet: padded matrices
            float lds[8];
        } lu;
    } sm;

    const int gid = blockIdx.x;
    const int tid = threadIdx.x;

    if (gid != 0) {
        // ---------------- conv path ----------------
        const int g4    = gid - 1;
        const int chunk = g4 & 63;          // 64 pixel chunks per plane
        const int k     = (g4 >> 6) & 7;
        const int b     = g4 >> 9;

        // Pack weights: ulonglong2 sm.w2[c*16 + dp] =
        //   { pack2(w[2dp][c]), pack2(w[2dp+1][c]) }
        unsigned long long* w2u = reinterpret_cast<unsigned long long*>(sm.w2);
        const float* wk = w + k * 1024;
        for (int i = tid; i < 1024; i += 256) {          // i = d*32 + c
            const int d = i >> 5, c = i & 31;
            const unsigned long long u =
                (unsigned long long)__float_as_uint(wk[i]);
            w2u[(c * 16 + (d >> 1)) * 2 + (d & 1)] = (u << 32) | u;
        }
        __syncthreads();

        const int  tpix  = tid & 63;        // pixel-thread within CTA
        const int  g     = tid >> 6;        // d-group: outputs [8g, 8g+8)
        const long pidx  = (long)chunk * 64 + tpix;      // ulonglong2 index
        const long base4 = ((long)b * 256 + (long)k * 32) * 4096L;

        const ulonglong2* __restrict__ xp =
            reinterpret_cast<const ulonglong2*>(x) + base4 + pidx;

        // 8 outputs x 2 f32x2 pixel-pairs
        unsigned long long acc[16];
#pragma unroll
        for (int i = 0; i < 16; ++i) acc[i] = 0ULL;

        const ulonglong2* __restrict__ wg = sm.w2 + g * 4;

        // Rotating register prefetch: 4 channel-planes in flight.
        ulonglong2 buf[4];
#pragma unroll
        for (int j = 0; j < 4; ++j) buf[j] = xp[(long)j * 4096];

#pragma unroll
        for (int c = 0; c < 32; ++c) {
            const ulonglong2 xv = buf[c & 3];
            if (c < 28) buf[c & 3] = xp[(long)(c + 4) * 4096];  // prefetch c+4
            const ulonglong2* wr = wg + c * 16;
#pragma unroll
            for (int j = 0; j < 4; ++j) {
                const ulonglong2 wv = wr[j];            // LDS.128 broadcast
                fma2(acc[4 * j + 0], xv.x, wv.x);
                fma2(acc[4 * j + 1], xv.y, wv.x);
                fma2(acc[4 * j + 2], xv.x, wv.y);
                fma2(acc[4 * j + 3], xv.y, wv.y);
            }
        }

        ulonglong2* __restrict__ zp =
            reinterpret_cast<ulonglong2*>(out) + base4 + pidx +
            (long)(8 * g) * 4096;
#pragma unroll
        for (int j = 0; j < 4; ++j) {
            zp[(long)(2 * j)     * 4096] = make_ulonglong2(acc[4 * j + 0], acc[4 * j + 1]);
            zp[(long)(2 * j + 1) * 4096] = make_ulonglong2(acc[4 * j + 2], acc[4 * j + 3]);
        }
    } else {
        // ---------------- logdet path (gid 0, runs in wave 1) ----------------
        // Warps 0..7: LU w/ partial pivot on matrix m = warp id.
        // Reference discards the sign: log|det| = sum log|pivot|.
        const int m    = tid >> 5;
        const int lane = tid & 31;

        for (int r = 0; r < 32; ++r)
            sm.lu.A[m][r][lane] = w[m * 1024 + r * 32 + lane];
        __syncwarp();

        float prod = 1.0f;   // product of pivot mantissas in [1,2)
        int   esum = 0;      // sum of pivot exponents
        for (int step = 0; step < 32; ++step) {
            // argmax |A[r][step]|, r >= step (abs-bits compare as uint)
            const unsigned v = (lane >= step)
                ? (__float_as_uint(sm.lu.A[m][lane][step]) & 0x7fffffffu)
                : 0u;
            const unsigned mx  = __reduce_max_sync(0xffffffffu, v);
            const unsigned bal = __ballot_sync(0xffffffffu, v == mx);
            const int pr = __ffs(bal) - 1;

            if (pr != step) {                // swap rows (lane owns a column)
                const float tswap = sm.lu.A[m][step][lane];
                sm.lu.A[m][step][lane] = sm.lu.A[m][pr][lane];
                sm.lu.A[m][pr][lane]   = tswap;
            }
            __syncwarp();

            const float piv = sm.lu.A[m][step][step];
            const unsigned pb = __float_as_uint(piv) & 0x7fffffffu;
            esum += (int)(pb >> 23) - 127;
            prod *= __uint_as_float((pb & 0x007fffffu) | 0x3f800000u);

            const float inv = 1.0f / piv;
            if (lane > step) {
                const float f = sm.lu.A[m][lane][step] * inv;
                for (int c2 = step + 1; c2 < 32; ++c2)
                    sm.lu.A[m][lane][c2] -= f * sm.lu.A[m][step][c2];
            }
            __syncwarp();
        }
        if (lane == 0)
            sm.lu.lds[m] = (float)esum * 0.6931471805599453f + logf(prod);
        __syncthreads();

        if (tid < 16) {
            float tot = 0.0f;
#pragma unroll
            for (int mm = 0; mm < 8; ++mm) tot += sm.lu.lds[mm];
            out[zn + tid] = ld_in[tid] + tot * 16384.0f;
        }
    }
}

// ---------------------------------------------------------------------------
extern "C" void kernel_launch(void* const* d_in, const int* in_sizes, int n_in,
                              void* d_out, int out_size) {
    const float* x  = (const float*)d_in[0];   // [16, 256, 128, 128]
    const float* w  = (const float*)d_in[1];   // [8, 32, 32]
    const float* ld = (const float*)d_in[2];   // [16]
    float* out = (float*)d_out;

    const long zn = (long)in_sizes[0];         // element count of z

    fused_kernel<<<8193, 256>>>(x, w, ld, out, zn);
    (void)n_in; (void)out_size;
}